// round 1
// baseline (speedup 1.0000x reference)
#include <cuda_runtime.h>

#define B_ 4
#define N_ 4096
#define C_ 1024
#define H_ 16
#define D_ 64
#define M1 (B_*N_)      // 16384 rows
#define N1 (3*C_)       // 3072 qkv cols
#define SPLITS 16
#define CHUNK (N_/SPLITS) // 256 rows per split

// ---- scratch (no allocs allowed; __device__ globals) ----
__device__ float g_qkv [(size_t)M1 * N1];          // 201 MB: qkv projection
__device__ float g_attn[(size_t)M1 * C_];          //  64 MB: attention out (B,N,C)
__device__ float g_kvp [64 * SPLITS * 64 * 64];    // split-K partial kv
__device__ float g_ksump[64 * SPLITS * 64];        // split-K partial ksum
__device__ float g_kv  [64 * 64 * 64];             // reduced kv per head
__device__ float g_ksum[64 * 64];                  // reduced ksum per head

// ============================================================
// Tiled SGEMM: C[M,N] = A[M,K] @ B[K,N]  (all row-major, fp32)
// 128x128 block, BK=8, 256 threads, 8x8 per-thread microtile.
// MODE 1: apply elu(x)+1 to columns < 2048 (q,k) in epilogue.
// MODE 2: add bias[col] in epilogue.
// M,N multiples of 128; K multiple of 8 (true for our shapes).
// ============================================================
template<int MODE>
__global__ __launch_bounds__(256) void sgemm128(
    const float* __restrict__ A, const float* __restrict__ Bm,
    float* __restrict__ C, int M, int N, int K,
    const float* __restrict__ bias)
{
    __shared__ float As[8][128];
    __shared__ float Bs[8][128];
    const int tid = threadIdx.x;
    const int tx = tid & 15;          // 16 col groups
    const int ty = tid >> 4;          // 16 row groups
    const int bx = blockIdx.x, by = blockIdx.y;

    const float* Ab = A + (size_t)by * 128 * K;
    const float* Bb = Bm + bx * 128;

    const int aRow = tid >> 1;         // 0..127
    const int aCol = (tid & 1) * 4;    // 0 or 4
    const int bRow = tid >> 5;         // 0..7
    const int bCol = (tid & 31) * 4;   // 0..124

    float acc[8][8] = {};

    for (int kk = 0; kk < K; kk += 8) {
        float4 a4 = *reinterpret_cast<const float4*>(Ab + (size_t)aRow * K + kk + aCol);
        As[aCol+0][aRow] = a4.x;
        As[aCol+1][aRow] = a4.y;
        As[aCol+2][aRow] = a4.z;
        As[aCol+3][aRow] = a4.w;
        *reinterpret_cast<float4*>(&Bs[bRow][bCol]) =
            *reinterpret_cast<const float4*>(Bb + (size_t)(kk + bRow) * N + bCol);
        __syncthreads();

        #pragma unroll
        for (int k = 0; k < 8; k++) {
            float ar[8], br[8];
            *reinterpret_cast<float4*>(ar)     = *reinterpret_cast<float4*>(&As[k][ty*8]);
            *reinterpret_cast<float4*>(ar + 4) = *reinterpret_cast<float4*>(&As[k][ty*8 + 4]);
            *reinterpret_cast<float4*>(br)     = *reinterpret_cast<float4*>(&Bs[k][tx*8]);
            *reinterpret_cast<float4*>(br + 4) = *reinterpret_cast<float4*>(&Bs[k][tx*8 + 4]);
            #pragma unroll
            for (int i = 0; i < 8; i++)
                #pragma unroll
                for (int j = 0; j < 8; j++)
                    acc[i][j] += ar[i] * br[j];
        }
        __syncthreads();
    }

    #pragma unroll
    for (int i = 0; i < 8; i++) {
        int row = by * 128 + ty * 8 + i;
        float* Crow = C + (size_t)row * N + bx * 128 + tx * 8;
        #pragma unroll
        for (int jj = 0; jj < 8; jj += 4) {
            float4 v;
            float* pv = &v.x;
            #pragma unroll
            for (int c = 0; c < 4; c++) {
                float val = acc[i][jj + c];
                if (MODE == 1) {
                    int col = bx * 128 + tx * 8 + jj + c;
                    if (col < 2 * C_)   // q and k columns: elu(x)+1
                        val = (val > 0.f) ? (val + 1.f) : expf(val);
                } else if (MODE == 2) {
                    val += bias[bx * 128 + tx * 8 + jj + c];
                }
                pv[c] = val;
            }
            *reinterpret_cast<float4*>(Crow + jj) = v;
        }
    }
}

// ============================================================
// Phase 2: per (b,h) split-K partials of kv[d][e] = sum_n k*v
// and ksum[d] = sum_n k.  grid (64 heads, SPLITS), 256 threads.
// Deterministic (no atomics).
// ============================================================
__global__ __launch_bounds__(256) void kv_partial_kernel(const float* __restrict__ qkv)
{
    int bh = blockIdx.x;
    int b = bh >> 4, h = bh & 15;
    int n0 = blockIdx.y * CHUNK;
    int tid = threadIdx.x;
    int d0 = (tid >> 4) * 4, e0 = (tid & 15) * 4;

    __shared__ float ks[32][64];
    __shared__ float vs[32][64];

    float acc[4][4] = {};
    float ksacc[4] = {0.f, 0.f, 0.f, 0.f};

    const float* base = qkv + (size_t)b * N_ * N1 + h * 64;

    for (int nt = 0; nt < CHUNK; nt += 32) {
        for (int l = tid; l < 512; l += 256) {       // 32 rows x 16 float4
            int r = l >> 4; int c = (l & 15) * 4;
            size_t off = (size_t)(n0 + nt + r) * N1 + c;
            *reinterpret_cast<float4*>(&ks[r][c]) =
                *reinterpret_cast<const float4*>(base + 1024 + off);
            *reinterpret_cast<float4*>(&vs[r][c]) =
                *reinterpret_cast<const float4*>(base + 2048 + off);
        }
        __syncthreads();
        #pragma unroll 4
        for (int r = 0; r < 32; r++) {
            float kr[4], vr[4];
            *reinterpret_cast<float4*>(kr) = *reinterpret_cast<float4*>(&ks[r][d0]);
            *reinterpret_cast<float4*>(vr) = *reinterpret_cast<float4*>(&vs[r][e0]);
            #pragma unroll
            for (int i = 0; i < 4; i++)
                #pragma unroll
                for (int j = 0; j < 4; j++)
                    acc[i][j] += kr[i] * vr[j];
            if (e0 == 0) {
                #pragma unroll
                for (int i = 0; i < 4; i++) ksacc[i] += kr[i];
            }
        }
        __syncthreads();
    }

    float* kvp = g_kvp + (size_t)(bh * SPLITS + blockIdx.y) * 4096;
    #pragma unroll
    for (int i = 0; i < 4; i++)
        #pragma unroll
        for (int j = 0; j < 4; j++)
            kvp[(d0 + i) * 64 + e0 + j] = acc[i][j];
    if (e0 == 0) {
        float* ksp = g_ksump + (size_t)(bh * SPLITS + blockIdx.y) * 64;
        #pragma unroll
        for (int i = 0; i < 4; i++) ksp[d0 + i] = ksacc[i];
    }
}

// ============================================================
// Phase 2b: reduce split partials.  grid (64), 256 threads.
// ============================================================
__global__ __launch_bounds__(256) void kv_reduce_kernel()
{
    int bh = blockIdx.x; int tid = threadIdx.x;
    for (int idx = tid; idx < 4096; idx += 256) {
        float s = 0.f;
        #pragma unroll
        for (int p = 0; p < SPLITS; p++)
            s += g_kvp[(size_t)(bh * SPLITS + p) * 4096 + idx];
        g_kv[(size_t)bh * 4096 + idx] = s;
    }
    if (tid < 64) {
        float s = 0.f;
        #pragma unroll
        for (int p = 0; p < SPLITS; p++)
            s += g_ksump[(size_t)(bh * SPLITS + p) * 64 + tid];
        g_ksum[bh * 64 + tid] = s;
    }
}

// ============================================================
// Phase 3: out[n,e] = (q[n,:] @ kv[:,e]) / (q[n,:]·ksum + 1e-6)
// Written straight into (B,N,C) layout for the output GEMM.
// grid (64 heads, 64 row-blocks of 64), 256 threads.
// ============================================================
__global__ __launch_bounds__(256) void q_apply_kernel(const float* __restrict__ qkv)
{
    int bh = blockIdx.x; int b = bh >> 4, h = bh & 15;
    int nb = blockIdx.y;
    int tid = threadIdx.x;

    __shared__ float kvs[64][64];
    __shared__ float qs [64][64];
    __shared__ float kss[64];

    {
        const float4* src = reinterpret_cast<const float4*>(g_kv + (size_t)bh * 4096);
        float4* dst = reinterpret_cast<float4*>(&kvs[0][0]);
        for (int idx = tid; idx < 1024; idx += 256) dst[idx] = src[idx];
    }
    if (tid < 64) kss[tid] = g_ksum[bh * 64 + tid];

    const float* qbase = qkv + ((size_t)b * N_ + nb * 64) * N1 + h * 64;
    for (int l = tid; l < 1024; l += 256) {          // 64 rows x 16 float4
        int r = l >> 4; int c = (l & 15) * 4;
        *reinterpret_cast<float4*>(&qs[r][c]) =
            *reinterpret_cast<const float4*>(qbase + (size_t)r * N1 + c);
    }
    __syncthreads();

    int te = tid & 63, rb = tid >> 6;
    for (int i = 0; i < 16; i++) {
        int r = rb + i * 4;
        float acc = 0.f, nacc = 0.f;
        #pragma unroll
        for (int d = 0; d < 64; d++) {
            float qv = qs[r][d];
            acc  += qv * kvs[d][te];
            nacc += qv * kss[d];
        }
        int n = nb * 64 + r;
        g_attn[((size_t)b * N_ + n) * C_ + h * 64 + te] = acc / (nacc + 1e-6f);
    }
}

// ============================================================
extern "C" void kernel_launch(void* const* d_in, const int* in_sizes, int n_in,
                              void* d_out, int out_size)
{
    const float* x     = (const float*)d_in[0];
    const float* W_qkv = (const float*)d_in[1];
    const float* W_out = (const float*)d_in[2];
    const float* b_out = (const float*)d_in[3];
    float* out = (float*)d_out;

    float *p_qkv, *p_attn;
    cudaGetSymbolAddress((void**)&p_qkv,  g_qkv);
    cudaGetSymbolAddress((void**)&p_attn, g_attn);

    // 1) qkv = x @ W_qkv, elu+1 fused on q,k columns
    sgemm128<1><<<dim3(N1 / 128, M1 / 128), 256>>>(x, W_qkv, p_qkv, M1, N1, C_, nullptr);
    // 2) kv / ksum split-K partials + reduce
    kv_partial_kernel<<<dim3(64, SPLITS), 256>>>(p_qkv);
    kv_reduce_kernel<<<64, 256>>>();
    // 3) numerator / normalizer / divide -> (B,N,C)
    q_apply_kernel<<<dim3(64, 64), 256>>>(p_qkv);
    // 4) out = attn @ W_out + b_out
    sgemm128<2><<<dim3(C_ / 128, M1 / 128), 256>>>(p_attn, W_out, out, M1, C_, C_, b_out);
}

// round 3
// speedup vs baseline: 2.3231x; 2.3231x over previous
#include <cuda_runtime.h>
#include <cstdint>

#define B_ 4
#define N_ 4096
#define C_ 1024
#define H_ 16
#define D_ 64
#define M1 (B_*N_)      // 16384 rows
#define N1 (3*C_)       // 3072 qkv cols
#define SPLITS 16
#define CHUNK (N_/SPLITS) // 256 rows per split

// ---- scratch (no allocs allowed; __device__ globals) ----
__device__ float g_qkv [(size_t)M1 * N1];          // 201 MB
__device__ float g_attn[(size_t)M1 * C_];          //  64 MB
__device__ float g_kvp [64 * SPLITS * 64 * 64];
__device__ float g_ksump[64 * SPLITS * 64];
__device__ float g_kv  [64 * 64 * 64];
__device__ float g_ksum[64 * 64];

// ============================================================
// tf32 helpers
// ============================================================
__device__ __forceinline__ uint32_t f2tf32(float x) {
    uint32_t r;
    asm("cvt.rna.tf32.f32 %0, %1;" : "=r"(r) : "f"(x));
    return r;
}

__device__ __forceinline__ void mma_tf32(float* c, const uint32_t* a, const uint32_t* b) {
    asm volatile(
        "mma.sync.aligned.m16n8k8.row.col.f32.tf32.tf32.f32 "
        "{%0,%1,%2,%3}, {%4,%5,%6,%7}, {%8,%9}, {%0,%1,%2,%3};"
        : "+f"(c[0]), "+f"(c[1]), "+f"(c[2]), "+f"(c[3])
        : "r"(a[0]), "r"(a[1]), "r"(a[2]), "r"(a[3]), "r"(b[0]), "r"(b[1]));
}

// ============================================================
// tf32 tensor-core GEMM: C[M,N] = A[M,K] @ B[K,N], fp32 in/out.
// 128x128 block tile, BK=32, 256 threads (8 warps in 2x4),
// warp tile 64x32 (4x4 of m16n8k8). Register-prefetch pipeline.
// MODE 1: elu(x)+1 on cols < 2048.  MODE 2: += bias[col].
// Requires M%128==0, N%128==0, K%32==0.
// ============================================================
template<int MODE>
__global__ __launch_bounds__(256) void tf32gemm(
    const float* __restrict__ A, const float* __restrict__ Bm,
    float* __restrict__ C, int M, int N, int K,
    const float* __restrict__ bias)
{
    __shared__ float As[128][36];   // [m][k], pad 36 -> conflict-free frag loads
    __shared__ float Bs[32][136];   // [k][n], pad 136 -> conflict-free frag loads

    const int tid  = threadIdx.x;
    const int lane = tid & 31;
    const int warp = tid >> 5;
    const int wr = warp >> 2;            // 0..1
    const int wc = warp & 3;             // 0..3
    const int bx = blockIdx.x, by = blockIdx.y;

    // global-load assignment
    const int aRow  = tid >> 1;          // 0..127
    const int aCol4 = (tid & 1) * 16;    // 0 or 16 (covers 16 k each)
    const int bRow  = tid >> 3;          // 0..31
    const int bCol  = (tid & 7) * 16;    // 0..112

    const float* Ab = A + (size_t)(by * 128 + aRow) * K;
    const float* Bb = Bm + (size_t)bx * 128;

    float4 pa[4], pb[4];
    #pragma unroll
    for (int i = 0; i < 4; i++) {
        pa[i] = *reinterpret_cast<const float4*>(Ab + aCol4 + i * 4);
        pb[i] = *reinterpret_cast<const float4*>(Bb + (size_t)(bRow) * N + bCol + i * 4);
    }

    float acc[4][4][4] = {};

    for (int kk = 0; kk < K; kk += 32) {
        // store prefetched tile to smem (converted to tf32 bit patterns)
        #pragma unroll
        for (int i = 0; i < 4; i++) {
            As[aRow][aCol4 + i*4 + 0] = __uint_as_float(f2tf32(pa[i].x));
            As[aRow][aCol4 + i*4 + 1] = __uint_as_float(f2tf32(pa[i].y));
            As[aRow][aCol4 + i*4 + 2] = __uint_as_float(f2tf32(pa[i].z));
            As[aRow][aCol4 + i*4 + 3] = __uint_as_float(f2tf32(pa[i].w));
            Bs[bRow][bCol + i*4 + 0] = __uint_as_float(f2tf32(pb[i].x));
            Bs[bRow][bCol + i*4 + 1] = __uint_as_float(f2tf32(pb[i].y));
            Bs[bRow][bCol + i*4 + 2] = __uint_as_float(f2tf32(pb[i].z));
            Bs[bRow][bCol + i*4 + 3] = __uint_as_float(f2tf32(pb[i].w));
        }
        __syncthreads();

        // prefetch next tile
        if (kk + 32 < K) {
            #pragma unroll
            for (int i = 0; i < 4; i++) {
                pa[i] = *reinterpret_cast<const float4*>(Ab + kk + 32 + aCol4 + i * 4);
                pb[i] = *reinterpret_cast<const float4*>(Bb + (size_t)(kk + 32 + bRow) * N + bCol + i * 4);
            }
        }

        // compute: 4 k-steps of 8
        #pragma unroll
        for (int ks = 0; ks < 32; ks += 8) {
            uint32_t af[4][4], bf[4][2];
            #pragma unroll
            for (int mt = 0; mt < 4; mt++) {
                int rb = wr * 64 + mt * 16 + (lane >> 2);
                af[mt][0] = __float_as_uint(As[rb    ][ks     + (lane & 3)]);
                af[mt][1] = __float_as_uint(As[rb + 8][ks     + (lane & 3)]);
                af[mt][2] = __float_as_uint(As[rb    ][ks + 4 + (lane & 3)]);
                af[mt][3] = __float_as_uint(As[rb + 8][ks + 4 + (lane & 3)]);
            }
            #pragma unroll
            for (int nt = 0; nt < 4; nt++) {
                int nb = wc * 32 + nt * 8 + (lane >> 2);
                bf[nt][0] = __float_as_uint(Bs[ks     + (lane & 3)][nb]);
                bf[nt][1] = __float_as_uint(Bs[ks + 4 + (lane & 3)][nb]);
            }
            #pragma unroll
            for (int mt = 0; mt < 4; mt++)
                #pragma unroll
                for (int nt = 0; nt < 4; nt++)
                    mma_tf32(acc[mt][nt], af[mt], bf[nt]);
        }
        __syncthreads();
    }

    // epilogue
    #pragma unroll
    for (int mt = 0; mt < 4; mt++) {
        #pragma unroll
        for (int nt = 0; nt < 4; nt++) {
            int row = by * 128 + wr * 64 + mt * 16 + (lane >> 2);
            int col = bx * 128 + wc * 32 + nt * 8 + (lane & 3) * 2;
            float v0 = acc[mt][nt][0], v1 = acc[mt][nt][1];
            float v2 = acc[mt][nt][2], v3 = acc[mt][nt][3];
            if (MODE == 1) {
                if (col < 2 * C_) {   // q,k columns (col even, pair stays one side)
                    v0 = (v0 > 0.f) ? (v0 + 1.f) : expf(v0);
                    v1 = (v1 > 0.f) ? (v1 + 1.f) : expf(v1);
                    v2 = (v2 > 0.f) ? (v2 + 1.f) : expf(v2);
                    v3 = (v3 > 0.f) ? (v3 + 1.f) : expf(v3);
                }
            } else if (MODE == 2) {
                float b0 = bias[col], b1 = bias[col + 1];
                v0 += b0; v1 += b1; v2 += b0; v3 += b1;
            }
            *reinterpret_cast<float2*>(C + (size_t)row * N + col)       = make_float2(v0, v1);
            *reinterpret_cast<float2*>(C + (size_t)(row + 8) * N + col) = make_float2(v2, v3);
        }
    }
}

// ============================================================
// Phase 2: per (b,h) split-K partials of kv[d][e] = sum_n k*v
// and ksum[d] = sum_n k.  Deterministic (no atomics).
// ============================================================
__global__ __launch_bounds__(256) void kv_partial_kernel(const float* __restrict__ qkv)
{
    int bh = blockIdx.x;
    int b = bh >> 4, h = bh & 15;
    int n0 = blockIdx.y * CHUNK;
    int tid = threadIdx.x;
    int d0 = (tid >> 4) * 4, e0 = (tid & 15) * 4;

    __shared__ float ks[32][64];
    __shared__ float vs[32][64];

    float acc[4][4] = {};
    float ksacc[4] = {0.f, 0.f, 0.f, 0.f};

    const float* base = qkv + (size_t)b * N_ * N1 + h * 64;

    for (int nt = 0; nt < CHUNK; nt += 32) {
        for (int l = tid; l < 512; l += 256) {
            int r = l >> 4; int c = (l & 15) * 4;
            size_t off = (size_t)(n0 + nt + r) * N1 + c;
            *reinterpret_cast<float4*>(&ks[r][c]) =
                *reinterpret_cast<const float4*>(base + 1024 + off);
            *reinterpret_cast<float4*>(&vs[r][c]) =
                *reinterpret_cast<const float4*>(base + 2048 + off);
        }
        __syncthreads();
        #pragma unroll 4
        for (int r = 0; r < 32; r++) {
            float kr[4], vr[4];
            *reinterpret_cast<float4*>(kr) = *reinterpret_cast<float4*>(&ks[r][d0]);
            *reinterpret_cast<float4*>(vr) = *reinterpret_cast<float4*>(&vs[r][e0]);
            #pragma unroll
            for (int i = 0; i < 4; i++)
                #pragma unroll
                for (int j = 0; j < 4; j++)
                    acc[i][j] += kr[i] * vr[j];
            if (e0 == 0) {
                #pragma unroll
                for (int i = 0; i < 4; i++) ksacc[i] += kr[i];
            }
        }
        __syncthreads();
    }

    float* kvp = g_kvp + (size_t)(bh * SPLITS + blockIdx.y) * 4096;
    #pragma unroll
    for (int i = 0; i < 4; i++)
        #pragma unroll
        for (int j = 0; j < 4; j++)
            kvp[(d0 + i) * 64 + e0 + j] = acc[i][j];
    if (e0 == 0) {
        float* ksp = g_ksump + (size_t)(bh * SPLITS + blockIdx.y) * 64;
        #pragma unroll
        for (int i = 0; i < 4; i++) ksp[d0 + i] = ksacc[i];
    }
}

__global__ __launch_bounds__(256) void kv_reduce_kernel()
{
    int bh = blockIdx.x; int tid = threadIdx.x;
    for (int idx = tid; idx < 4096; idx += 256) {
        float s = 0.f;
        #pragma unroll
        for (int p = 0; p < SPLITS; p++)
            s += g_kvp[(size_t)(bh * SPLITS + p) * 4096 + idx];
        g_kv[(size_t)bh * 4096 + idx] = s;
    }
    if (tid < 64) {
        float s = 0.f;
        #pragma unroll
        for (int p = 0; p < SPLITS; p++)
            s += g_ksump[(size_t)(bh * SPLITS + p) * 64 + tid];
        g_ksum[bh * 64 + tid] = s;
    }
}

// ============================================================
// Phase 3: out[n,e] = (q[n,:] @ kv[:,e]) / (q[n,:]·ksum + 1e-6)
// 4x4 microtile per thread; written into (B,N,C) layout.
// grid (64 heads, 64 row-blocks of 64), 256 threads.
// ============================================================
__global__ __launch_bounds__(256) void q_apply_kernel(const float* __restrict__ qkv)
{
    int bh = blockIdx.x; int b = bh >> 4, h = bh & 15;
    int nb = blockIdx.y;
    int tid = threadIdx.x;

    __shared__ float kvs[64][68];   // kvs[d][e]
    __shared__ float qs [64][68];   // qs[r][d]
    __shared__ float kss[64];

    {
        const float* src = g_kv + (size_t)bh * 4096;
        for (int l = tid; l < 1024; l += 256) {
            int d = l >> 4; int e = (l & 15) * 4;
            *reinterpret_cast<float4*>(&kvs[d][e]) =
                *reinterpret_cast<const float4*>(src + d * 64 + e);
        }
    }
    if (tid < 64) kss[tid] = g_ksum[bh * 64 + tid];

    const float* qbase = qkv + ((size_t)b * N_ + nb * 64) * N1 + h * 64;
    for (int l = tid; l < 1024; l += 256) {
        int r = l >> 4; int c = (l & 15) * 4;
        *reinterpret_cast<float4*>(&qs[r][c]) =
            *reinterpret_cast<const float4*>(qbase + (size_t)r * N1 + c);
    }
    __syncthreads();

    const int r0 = (tid >> 4) * 4;
    const int e0 = (tid & 15) * 4;

    float acc[4][4] = {};
    float nacc[4] = {0.f, 0.f, 0.f, 0.f};

    #pragma unroll 8
    for (int d = 0; d < 64; d++) {
        float qv[4], kvr[4];
        #pragma unroll
        for (int i = 0; i < 4; i++) qv[i] = qs[r0 + i][d];
        *reinterpret_cast<float4*>(kvr) = *reinterpret_cast<float4*>(&kvs[d][e0]);
        float ksd = kss[d];
        #pragma unroll
        for (int i = 0; i < 4; i++) {
            nacc[i] += qv[i] * ksd;
            #pragma unroll
            for (int j = 0; j < 4; j++)
                acc[i][j] += qv[i] * kvr[j];
        }
    }

    #pragma unroll
    for (int i = 0; i < 4; i++) {
        float inv = 1.f / (nacc[i] + 1e-6f);
        float4 v = make_float4(acc[i][0] * inv, acc[i][1] * inv,
                               acc[i][2] * inv, acc[i][3] * inv);
        int n = nb * 64 + r0 + i;
        *reinterpret_cast<float4*>(
            &g_attn[((size_t)b * N_ + n) * C_ + h * 64 + e0]) = v;
    }
}

// ============================================================
extern "C" void kernel_launch(void* const* d_in, const int* in_sizes, int n_in,
                              void* d_out, int out_size)
{
    const float* x     = (const float*)d_in[0];
    const float* W_qkv = (const float*)d_in[1];
    const float* W_out = (const float*)d_in[2];
    const float* b_out = (const float*)d_in[3];
    float* out = (float*)d_out;

    float *p_qkv, *p_attn;
    cudaGetSymbolAddress((void**)&p_qkv,  g_qkv);
    cudaGetSymbolAddress((void**)&p_attn, g_attn);

    // 1) qkv = x @ W_qkv (tf32 tensor cores), elu+1 fused on q,k columns
    tf32gemm<1><<<dim3(N1 / 128, M1 / 128), 256>>>(x, W_qkv, p_qkv, M1, N1, C_, nullptr);
    // 2) kv / ksum split-K partials + reduce (fp32 exact)
    kv_partial_kernel<<<dim3(64, SPLITS), 256>>>(p_qkv);
    kv_reduce_kernel<<<64, 256>>>();
    // 3) numerator / normalizer / divide -> (B,N,C)
    q_apply_kernel<<<dim3(64, 64), 256>>>(p_qkv);
    // 4) out = attn @ W_out + b_out (tf32 tensor cores)
    tf32gemm<2><<<dim3(C_ / 128, M1 / 128), 256>>>(p_attn, W_out, out, M1, C_, C_, b_out);
}

// round 5
// speedup vs baseline: 3.0145x; 1.2976x over previous
#include <cuda_runtime.h>
#include <cstdint>

#define B_ 4
#define N_ 4096
#define C_ 1024
#define H_ 16
#define D_ 64
#define M1 (B_*N_)      // 16384 rows
#define N1 (3*C_)       // 3072 qkv cols
#define SPLITS 16
#define CHUNK (N_/SPLITS) // 256 rows per split

// ---- scratch (no allocs allowed; __device__ globals) ----
__device__ float g_qkv [(size_t)M1 * N1];          // 201 MB
__device__ float g_attn[(size_t)M1 * C_];          //  64 MB
__device__ float g_kvp [64 * SPLITS * 64 * 64];
__device__ float g_ksump[64 * SPLITS * 64];
__device__ float g_kv  [64 * 64 * 64];
__device__ float g_ksum[64 * 64];

// ============================================================
// tf32 helpers
// ============================================================
__device__ __forceinline__ float f2tf32f(float x) {
    uint32_t r;
    asm("cvt.rna.tf32.f32 %0, %1;" : "=r"(r) : "f"(x));
    return __uint_as_float(r);
}

__device__ __forceinline__ void mma_tf32(float* c, const uint32_t* a, const uint32_t* b) {
    asm volatile(
        "mma.sync.aligned.m16n8k8.row.col.f32.tf32.tf32.f32 "
        "{%0,%1,%2,%3}, {%4,%5,%6,%7}, {%8,%9}, {%0,%1,%2,%3};"
        : "+f"(c[0]), "+f"(c[1]), "+f"(c[2]), "+f"(c[3])
        : "r"(a[0]), "r"(a[1]), "r"(a[2]), "r"(a[3]), "r"(b[0]), "r"(b[1]));
}

// ============================================================
// tf32 tensor-core GEMM: C[M,N] = A[M,K] @ B[K,N], fp32 in/out.
// 128x128 block tile, BK=16, double-buffered smem, 256 threads
// (8 warps, 2x4), warp tile 64x32 (4x4 of m16n8k8).
// Coalesced linear load assignment; conflict-free smem banking.
// MODE 1: elu(x)+1 on cols < 2048.  MODE 2: += bias[col].
// Requires M%128==0, N%128==0, K%16==0.
// ============================================================
#define BK 16
template<int MODE>
__global__ __launch_bounds__(256, 2) void tf32gemm(
    const float* __restrict__ A, const float* __restrict__ Bm,
    float* __restrict__ C, int M, int N, int K,
    const float* __restrict__ bias)
{
    __shared__ float As[2][128][20];   // [m][k], pad 20 -> conflict-free frag loads
    __shared__ float Bs[2][BK][136];   // [k][n], pad 136 -> conflict-free frag loads

    const int tid  = threadIdx.x;
    const int lane = tid & 31;
    const int warp = tid >> 5;
    const int wr = warp >> 2;            // 0..1
    const int wc = warp & 3;             // 0..3
    const int bx = blockIdx.x, by = blockIdx.y;
    const int la3 = lane & 3;
    const int l4  = lane >> 2;

    // linear, fully-coalesced global-load assignment
    // A tile 128x16: 512 float4, 2/thread: row = idx>>2, col4 = idx&3
    // B tile 16x128: 512 float4, 2/thread: row = idx>>5, col4 = idx&31
    const int aRow0 = tid >> 2;          // +64 per i
    const int aCol  = (tid & 3) * 4;
    const int bRow0 = tid >> 5;          // +8 per i
    const int bCol  = (tid & 31) * 4;

    const float* Abase = A + (size_t)(by * 128) * K;
    const float* Bbase = Bm + (size_t)bx * 128;

    float4 pa[2], pb[2];
    #pragma unroll
    for (int i = 0; i < 2; i++) {
        pa[i] = *reinterpret_cast<const float4*>(Abase + (size_t)(aRow0 + 64*i) * K + aCol);
        pb[i] = *reinterpret_cast<const float4*>(Bbase + (size_t)(bRow0 + 8*i) * N + bCol);
    }

    // store tile (with tf32 conversion) into buffer `buf`
    #define STORE_TILE(buf)                                                  \
        do {                                                                 \
            _Pragma("unroll")                                                \
            for (int i = 0; i < 2; i++) {                                    \
                As[buf][aRow0 + 64*i][aCol + 0] = f2tf32f(pa[i].x);          \
                As[buf][aRow0 + 64*i][aCol + 1] = f2tf32f(pa[i].y);          \
                As[buf][aRow0 + 64*i][aCol + 2] = f2tf32f(pa[i].z);          \
                As[buf][aRow0 + 64*i][aCol + 3] = f2tf32f(pa[i].w);          \
                Bs[buf][bRow0 + 8*i][bCol + 0] = f2tf32f(pb[i].x);           \
                Bs[buf][bRow0 + 8*i][bCol + 1] = f2tf32f(pb[i].y);           \
                Bs[buf][bRow0 + 8*i][bCol + 2] = f2tf32f(pb[i].z);           \
                Bs[buf][bRow0 + 8*i][bCol + 3] = f2tf32f(pb[i].w);           \
            }                                                                \
        } while (0)

    STORE_TILE(0);
    __syncthreads();

    float acc[4][4][4] = {};
    const int nTiles = K / BK;

    for (int t = 0; t < nTiles; t++) {
        const int cur = t & 1;

        // prefetch next tile into registers (LDG issued before compute)
        if (t + 1 < nTiles) {
            const int kk = (t + 1) * BK;
            #pragma unroll
            for (int i = 0; i < 2; i++) {
                pa[i] = *reinterpret_cast<const float4*>(Abase + (size_t)(aRow0 + 64*i) * K + kk + aCol);
                pb[i] = *reinterpret_cast<const float4*>(Bbase + (size_t)(kk + bRow0 + 8*i) * N + bCol);
            }
        }

        // compute: 2 k-steps of 8
        #pragma unroll
        for (int ks = 0; ks < BK; ks += 8) {
            uint32_t af[4][4], bf[4][2];
            #pragma unroll
            for (int mt = 0; mt < 4; mt++) {
                int rb = wr * 64 + mt * 16 + l4;
                af[mt][0] = __float_as_uint(As[cur][rb    ][ks     + la3]);
                af[mt][1] = __float_as_uint(As[cur][rb + 8][ks     + la3]);
                af[mt][2] = __float_as_uint(As[cur][rb    ][ks + 4 + la3]);
                af[mt][3] = __float_as_uint(As[cur][rb + 8][ks + 4 + la3]);
            }
            #pragma unroll
            for (int nt = 0; nt < 4; nt++) {
                int nb = wc * 32 + nt * 8 + l4;
                bf[nt][0] = __float_as_uint(Bs[cur][ks     + la3][nb]);
                bf[nt][1] = __float_as_uint(Bs[cur][ks + 4 + la3][nb]);
            }
            #pragma unroll
            for (int mt = 0; mt < 4; mt++)
                #pragma unroll
                for (int nt = 0; nt < 4; nt++)
                    mma_tf32(acc[mt][nt], af[mt], bf[nt]);
        }

        // store prefetched tile to the idle buffer
        if (t + 1 < nTiles) STORE_TILE(cur ^ 1);
        __syncthreads();
    }

    // epilogue
    #pragma unroll
    for (int mt = 0; mt < 4; mt++) {
        #pragma unroll
        for (int nt = 0; nt < 4; nt++) {
            int row = by * 128 + wr * 64 + mt * 16 + l4;
            int col = bx * 128 + wc * 32 + nt * 8 + la3 * 2;
            float v0 = acc[mt][nt][0], v1 = acc[mt][nt][1];
            float v2 = acc[mt][nt][2], v3 = acc[mt][nt][3];
            if (MODE == 1) {
                if (col < 2 * C_) {   // q,k columns: elu(x)+1
                    v0 = (v0 > 0.f) ? (v0 + 1.f) : __expf(v0);
                    v1 = (v1 > 0.f) ? (v1 + 1.f) : __expf(v1);
                    v2 = (v2 > 0.f) ? (v2 + 1.f) : __expf(v2);
                    v3 = (v3 > 0.f) ? (v3 + 1.f) : __expf(v3);
                }
            } else if (MODE == 2) {
                float b0 = bias[col], b1 = bias[col + 1];
                v0 += b0; v1 += b1; v2 += b0; v3 += b1;
            }
            *reinterpret_cast<float2*>(C + (size_t)row * N + col)       = make_float2(v0, v1);
            *reinterpret_cast<float2*>(C + (size_t)(row + 8) * N + col) = make_float2(v2, v3);
        }
    }
}

// ============================================================
// Phase 2: per (b,h) split-K partials of kv[d][e] = sum_n k*v
// and ksum[d] = sum_n k.  Deterministic (no atomics).
// ============================================================
__global__ __launch_bounds__(256) void kv_partial_kernel(const float* __restrict__ qkv)
{
    int bh = blockIdx.x;
    int b = bh >> 4, h = bh & 15;
    int n0 = blockIdx.y * CHUNK;
    int tid = threadIdx.x;
    int d0 = (tid >> 4) * 4, e0 = (tid & 15) * 4;

    __shared__ float ks[32][64];
    __shared__ float vs[32][64];

    float acc[4][4] = {};
    float ksacc[4] = {0.f, 0.f, 0.f, 0.f};

    const float* base = qkv + (size_t)b * N_ * N1 + h * 64;

    for (int nt = 0; nt < CHUNK; nt += 32) {
        for (int l = tid; l < 512; l += 256) {
            int r = l >> 4; int c = (l & 15) * 4;
            size_t off = (size_t)(n0 + nt + r) * N1 + c;
            *reinterpret_cast<float4*>(&ks[r][c]) =
                *reinterpret_cast<const float4*>(base + 1024 + off);
            *reinterpret_cast<float4*>(&vs[r][c]) =
                *reinterpret_cast<const float4*>(base + 2048 + off);
        }
        __syncthreads();
        #pragma unroll 4
        for (int r = 0; r < 32; r++) {
            float kr[4], vr[4];
            *reinterpret_cast<float4*>(kr) = *reinterpret_cast<float4*>(&ks[r][d0]);
            *reinterpret_cast<float4*>(vr) = *reinterpret_cast<float4*>(&vs[r][e0]);
            #pragma unroll
            for (int i = 0; i < 4; i++)
                #pragma unroll
                for (int j = 0; j < 4; j++)
                    acc[i][j] += kr[i] * vr[j];
            if (e0 == 0) {
                #pragma unroll
                for (int i = 0; i < 4; i++) ksacc[i] += kr[i];
            }
        }
        __syncthreads();
    }

    float* kvp = g_kvp + (size_t)(bh * SPLITS + blockIdx.y) * 4096;
    #pragma unroll
    for (int i = 0; i < 4; i++)
        #pragma unroll
        for (int j = 0; j < 4; j++)
            kvp[(d0 + i) * 64 + e0 + j] = acc[i][j];
    if (e0 == 0) {
        float* ksp = g_ksump + (size_t)(bh * SPLITS + blockIdx.y) * 64;
        #pragma unroll
        for (int i = 0; i < 4; i++) ksp[d0 + i] = ksacc[i];
    }
}

__global__ __launch_bounds__(256) void kv_reduce_kernel()
{
    int bh = blockIdx.x; int tid = threadIdx.x;
    for (int idx = tid; idx < 4096; idx += 256) {
        float s = 0.f;
        #pragma unroll
        for (int p = 0; p < SPLITS; p++)
            s += g_kvp[(size_t)(bh * SPLITS + p) * 4096 + idx];
        g_kv[(size_t)bh * 4096 + idx] = s;
    }
    if (tid < 64) {
        float s = 0.f;
        #pragma unroll
        for (int p = 0; p < SPLITS; p++)
            s += g_ksump[(size_t)(bh * SPLITS + p) * 64 + tid];
        g_ksum[bh * 64 + tid] = s;
    }
}

// ============================================================
// Phase 3: out[n,e] = (q[n,:] @ kv[:,e]) / (q[n,:]·ksum + 1e-6)
// 4x4 microtile per thread; written into (B,N,C) layout.
// ============================================================
__global__ __launch_bounds__(256) void q_apply_kernel(const float* __restrict__ qkv)
{
    int bh = blockIdx.x; int b = bh >> 4, h = bh & 15;
    int nb = blockIdx.y;
    int tid = threadIdx.x;

    __shared__ float kvs[64][68];   // kvs[d][e]
    __shared__ float qs [64][68];   // qs[r][d]
    __shared__ float kss[64];

    {
        const float* src = g_kv + (size_t)bh * 4096;
        for (int l = tid; l < 1024; l += 256) {
            int d = l >> 4; int e = (l & 15) * 4;
            *reinterpret_cast<float4*>(&kvs[d][e]) =
                *reinterpret_cast<const float4*>(src + d * 64 + e);
        }
    }
    if (tid < 64) kss[tid] = g_ksum[bh * 64 + tid];

    const float* qbase = qkv + ((size_t)b * N_ + nb * 64) * N1 + h * 64;
    for (int l = tid; l < 1024; l += 256) {
        int r = l >> 4; int c = (l & 15) * 4;
        *reinterpret_cast<float4*>(&qs[r][c]) =
            *reinterpret_cast<const float4*>(qbase + (size_t)r * N1 + c);
    }
    __syncthreads();

    const int r0 = (tid >> 4) * 4;
    const int e0 = (tid & 15) * 4;

    float acc[4][4] = {};
    float nacc[4] = {0.f, 0.f, 0.f, 0.f};

    #pragma unroll 8
    for (int d = 0; d < 64; d++) {
        float qv[4], kvr[4];
        #pragma unroll
        for (int i = 0; i < 4; i++) qv[i] = qs[r0 + i][d];
        *reinterpret_cast<float4*>(kvr) = *reinterpret_cast<float4*>(&kvs[d][e0]);
        float ksd = kss[d];
        #pragma unroll
        for (int i = 0; i < 4; i++) {
            nacc[i] += qv[i] * ksd;
            #pragma unroll
            for (int j = 0; j < 4; j++)
                acc[i][j] += qv[i] * kvr[j];
        }
    }

    #pragma unroll
    for (int i = 0; i < 4; i++) {
        float inv = 1.f / (nacc[i] + 1e-6f);
        float4 v = make_float4(acc[i][0] * inv, acc[i][1] * inv,
                               acc[i][2] * inv, acc[i][3] * inv);
        int n = nb * 64 + r0 + i;
        *reinterpret_cast<float4*>(
            &g_attn[((size_t)b * N_ + n) * C_ + h * 64 + e0]) = v;
    }
}

// ============================================================
extern "C" void kernel_launch(void* const* d_in, const int* in_sizes, int n_in,
                              void* d_out, int out_size)
{
    const float* x     = (const float*)d_in[0];
    const float* W_qkv = (const float*)d_in[1];
    const float* W_out = (const float*)d_in[2];
    const float* b_out = (const float*)d_in[3];
    float* out = (float*)d_out;

    float *p_qkv, *p_attn;
    cudaGetSymbolAddress((void**)&p_qkv,  g_qkv);
    cudaGetSymbolAddress((void**)&p_attn, g_attn);

    // 1) qkv = x @ W_qkv (tf32 tensor cores), elu+1 fused on q,k columns
    tf32gemm<1><<<dim3(N1 / 128, M1 / 128), 256>>>(x, W_qkv, p_qkv, M1, N1, C_, nullptr);
    // 2) kv / ksum split-K partials + reduce (fp32 exact)
    kv_partial_kernel<<<dim3(64, SPLITS), 256>>>(p_qkv);
    kv_reduce_kernel<<<64, 256>>>();
    // 3) numerator / normalizer / divide -> (B,N,C)
    q_apply_kernel<<<dim3(64, 64), 256>>>(p_qkv);
    // 4) out = attn @ W_out + b_out (tf32 tensor cores)
    tf32gemm<2><<<dim3(C_ / 128, M1 / 128), 256>>>(p_attn, W_out, out, M1, C_, C_, b_out);
}